// round 3
// baseline (speedup 1.0000x reference)
#include <cuda_runtime.h>
#include <cuda_bf16.h>
#include <cstdint>

#define Nn   50000
#define Ee   800000
#define F_IN 512
#define H1   256
#define H2   32
#define Cc   16

// ---------------- scratch (device globals; no allocations allowed) ----------
static __device__ float g_h1[(size_t)Nn * H1];   // x @ W1
static __device__ float g_x2[(size_t)Nn * H1];   // relu(agg1 + b1)
static __device__ float g_h2[(size_t)Nn * H2];   // x2 @ W2
static __device__ float g_x3[(size_t)Nn * H2];   // relu(agg2 + b2)
static __device__ float g_h3[(size_t)Nn * Cc];   // x3 @ W3
static __device__ float g_dinv[Nn];
static __device__ int   g_deg[Nn];
static __device__ int   g_incl[Nn];
static __device__ int   g_rowstart[Nn];
static __device__ int   g_fill[Nn];
static __device__ int   g_col[Ee];
static __device__ int   g_blocksums[64];
static __device__ int   g_is64;

// ---------------- edge-index dtype detection --------------------------------
// int64 little-endian with values < 2^31  => every odd 32-bit word is 0.
// int32 => odd words are edge indices (uniform in [0,50000)), ~never all zero.
__global__ void k_detect(const unsigned int* __restrict__ w) {
    if (threadIdx.x == 0 && blockIdx.x == 0) {
        int is64 = 1;
        for (int i = 1; i < 512; i += 2) {
            if (w[i] != 0u) { is64 = 0; break; }
        }
        g_is64 = is64;
    }
}

__device__ __forceinline__ int load_idx(const void* __restrict__ ei, long long idx) {
    if (g_is64) return (int)((const long long*)ei)[idx];
    return ((const int*)ei)[idx];
}

// ---------------- CSR build --------------------------------------------------
__global__ void k_zero_deg() {
    int i = blockIdx.x * blockDim.x + threadIdx.x;
    if (i < Nn) g_deg[i] = 0;
}

__global__ void k_count(const void* __restrict__ ei) {
    int e = blockIdx.x * blockDim.x + threadIdx.x;
    if (e < Ee) {
        int d = load_idx(ei, (long long)Ee + e);
        atomicAdd(&g_deg[d], 1);
    }
}

__global__ void k_scan1() {
    __shared__ int s[1024];
    int t = threadIdx.x;
    int i = blockIdx.x * 1024 + t;
    s[t] = (i < Nn) ? g_deg[i] : 0;
    __syncthreads();
    for (int off = 1; off < 1024; off <<= 1) {
        int add = (t >= off) ? s[t - off] : 0;
        __syncthreads();
        s[t] += add;
        __syncthreads();
    }
    if (i < Nn) g_incl[i] = s[t];
    if (t == 1023) g_blocksums[blockIdx.x] = s[1023];
}

__global__ void k_scan2(int nblocks) {
    if (threadIdx.x == 0) {
        int run = 0;
        for (int i = 0; i < nblocks; i++) {
            int v = g_blocksums[i];
            g_blocksums[i] = run;
            run += v;
        }
    }
}

__global__ void k_scan3() {
    int i = blockIdx.x * blockDim.x + threadIdx.x;
    if (i < Nn) {
        int deg = g_deg[i];
        int start = g_incl[i] - deg + g_blocksums[i >> 10];
        g_rowstart[i] = start;
        g_fill[i] = start;
        g_dinv[i] = rsqrtf((float)(deg + 1));   // +1 self loop
    }
}

__global__ void k_scatter(const void* __restrict__ ei) {
    int e = blockIdx.x * blockDim.x + threadIdx.x;
    if (e < Ee) {
        int s = load_idx(ei, e);
        int d = load_idx(ei, (long long)Ee + e);
        int pos = atomicAdd(&g_fill[d], 1);
        g_col[pos] = s;
    }
}

// ---------------- GEMM1: [Nn,512] x [512,256] -> g_h1 -----------------------
__global__ void k_gemm1(const float* __restrict__ A, const float* __restrict__ B) {
    __shared__ float As[16][64];
    __shared__ float Bs[16][64];
    int tid = threadIdx.x;
    int tx = tid & 15, ty = tid >> 4;
    int rowBase = blockIdx.y * 64;
    int colBase = blockIdx.x * 64;
    float acc[4][4] = {};
    int aRow = tid >> 2;
    int aK4 = (tid & 3) * 4;
    int bK = tid >> 4;
    int bC = (tid & 15) * 4;

    for (int k0 = 0; k0 < F_IN; k0 += 16) {
        int gr = rowBase + aRow;
        float4 av = make_float4(0.f, 0.f, 0.f, 0.f);
        if (gr < Nn) av = *(const float4*)(A + (size_t)gr * F_IN + k0 + aK4);
        As[aK4 + 0][aRow] = av.x;
        As[aK4 + 1][aRow] = av.y;
        As[aK4 + 2][aRow] = av.z;
        As[aK4 + 3][aRow] = av.w;
        *(float4*)(&Bs[bK][bC]) = *(const float4*)(B + (size_t)(k0 + bK) * H1 + colBase + bC);
        __syncthreads();
#pragma unroll
        for (int kk = 0; kk < 16; kk++) {
            float4 a = *(const float4*)(&As[kk][ty * 4]);
            float4 b = *(const float4*)(&Bs[kk][tx * 4]);
            acc[0][0] += a.x * b.x; acc[0][1] += a.x * b.y; acc[0][2] += a.x * b.z; acc[0][3] += a.x * b.w;
            acc[1][0] += a.y * b.x; acc[1][1] += a.y * b.y; acc[1][2] += a.y * b.z; acc[1][3] += a.y * b.w;
            acc[2][0] += a.z * b.x; acc[2][1] += a.z * b.y; acc[2][2] += a.z * b.z; acc[2][3] += a.z * b.w;
            acc[3][0] += a.w * b.x; acc[3][1] += a.w * b.y; acc[3][2] += a.w * b.z; acc[3][3] += a.w * b.w;
        }
        __syncthreads();
    }
#pragma unroll
    for (int i = 0; i < 4; i++) {
        int r = rowBase + ty * 4 + i;
        if (r < Nn) {
            float4 v = make_float4(acc[i][0], acc[i][1], acc[i][2], acc[i][3]);
            *(float4*)(g_h1 + (size_t)r * H1 + colBase + tx * 4) = v;
        }
    }
}

// ---------------- GEMM2: g_x2 [Nn,256] x W2 [256,32] -> g_h2 ----------------
__global__ void k_gemm2(const float* __restrict__ W) {
    __shared__ float sA[32][64];
    __shared__ float sW[64][32];
    int tid = threadIdx.x;
    int r = tid >> 3;
    int c4 = (tid & 7) * 4;
    int row0 = blockIdx.x * 32;
    float acc[4] = {0.f, 0.f, 0.f, 0.f};

    for (int k0 = 0; k0 < H1; k0 += 64) {
        for (int i = tid; i < 32 * 16; i += 256) {
            int rr = i >> 4;
            int kk4 = (i & 15) * 4;
            int grow = row0 + rr;
            float4 v = make_float4(0.f, 0.f, 0.f, 0.f);
            if (grow < Nn) v = *(const float4*)(g_x2 + (size_t)grow * H1 + k0 + kk4);
            *(float4*)(&sA[rr][kk4]) = v;
        }
        for (int i = tid; i < 512; i += 256) {
            int kk = i >> 3;
            int cc4 = (i & 7) * 4;
            *(float4*)(&sW[kk][cc4]) = *(const float4*)(W + (size_t)(k0 + kk) * H2 + cc4);
        }
        __syncthreads();
#pragma unroll
        for (int kk = 0; kk < 64; kk++) {
            float a = sA[r][kk];
            acc[0] += a * sW[kk][c4 + 0];
            acc[1] += a * sW[kk][c4 + 1];
            acc[2] += a * sW[kk][c4 + 2];
            acc[3] += a * sW[kk][c4 + 3];
        }
        __syncthreads();
    }
    int row = row0 + r;
    if (row < Nn) {
        float4 v = make_float4(acc[0], acc[1], acc[2], acc[3]);
        *(float4*)(g_h2 + (size_t)row * H2 + c4) = v;
    }
}

// ---------------- GEMM3: g_x3 [Nn,32] x W3 [32,16] -> g_h3 ------------------
__global__ void k_gemm3(const float* __restrict__ W) {
    __shared__ float sW[32 * 16];
    int tid = threadIdx.x;
    for (int i = tid; i < 32 * 16; i += 256) sW[i] = W[i];
    __syncthreads();
    int row = blockIdx.x * 256 + tid;
    if (row >= Nn) return;
    float acc[16];
#pragma unroll
    for (int c = 0; c < 16; c++) acc[c] = 0.f;
    const float4* ap = (const float4*)(g_x3 + (size_t)row * H2);
#pragma unroll
    for (int k4 = 0; k4 < 8; k4++) {
        float4 a = ap[k4];
        int k = k4 * 4;
#pragma unroll
        for (int c = 0; c < 16; c++) {
            acc[c] += a.x * sW[(k + 0) * 16 + c];
            acc[c] += a.y * sW[(k + 1) * 16 + c];
            acc[c] += a.z * sW[(k + 2) * 16 + c];
            acc[c] += a.w * sW[(k + 3) * 16 + c];
        }
    }
    float* op = g_h3 + (size_t)row * Cc;
#pragma unroll
    for (int c4 = 0; c4 < 4; c4++) {
        float4 v = make_float4(acc[c4 * 4 + 0], acc[c4 * 4 + 1], acc[c4 * 4 + 2], acc[c4 * 4 + 3]);
        *(float4*)(op + c4 * 4) = v;
    }
}

// ---------------- Aggregation: out[d] = dinv[d]*Sum(dinv[s]*h[s]) + b -------
// All scratch buffers referenced DIRECTLY in device code (never passed from host).

// Layer 1: h = g_h1 (F=256), out = g_x2, relu. Warp per node, 8 floats/lane.
__global__ void k_agg256(const float* __restrict__ bias) {
    int warp = threadIdx.x >> 5;
    int lane = threadIdx.x & 31;
    int node = blockIdx.x * 8 + warp;
    if (node >= Nn) return;
    float wd = g_dinv[node];
    const float4* hp = (const float4*)(g_h1 + (size_t)node * 256);
    float4 a0 = hp[lane];
    float4 a1 = hp[32 + lane];
    float4 acc0 = make_float4(a0.x * wd, a0.y * wd, a0.z * wd, a0.w * wd);
    float4 acc1 = make_float4(a1.x * wd, a1.y * wd, a1.z * wd, a1.w * wd);
    int beg = g_rowstart[node];
    int cnt = g_deg[node];
    for (int j = 0; j < cnt; j++) {
        int s = g_col[beg + j];
        float w = g_dinv[s];
        const float4* sp = (const float4*)(g_h1 + (size_t)s * 256);
        float4 v0 = sp[lane];
        float4 v1 = sp[32 + lane];
        acc0.x += w * v0.x; acc0.y += w * v0.y; acc0.z += w * v0.z; acc0.w += w * v0.w;
        acc1.x += w * v1.x; acc1.y += w * v1.y; acc1.z += w * v1.z; acc1.w += w * v1.w;
    }
    float4 b0 = ((const float4*)bias)[lane];
    float4 b1 = ((const float4*)bias)[32 + lane];
    float4 r0 = make_float4(fmaxf(acc0.x * wd + b0.x, 0.f), fmaxf(acc0.y * wd + b0.y, 0.f),
                            fmaxf(acc0.z * wd + b0.z, 0.f), fmaxf(acc0.w * wd + b0.w, 0.f));
    float4 r1 = make_float4(fmaxf(acc1.x * wd + b1.x, 0.f), fmaxf(acc1.y * wd + b1.y, 0.f),
                            fmaxf(acc1.z * wd + b1.z, 0.f), fmaxf(acc1.w * wd + b1.w, 0.f));
    float4* op = (float4*)(g_x2 + (size_t)node * 256);
    op[lane] = r0;
    op[32 + lane] = r1;
}

// Layer 2: h = g_h2 (F=32), out = g_x3, relu. Warp per node, 1 float/lane.
__global__ void k_agg32(const float* __restrict__ bias) {
    int warp = threadIdx.x >> 5;
    int lane = threadIdx.x & 31;
    int node = blockIdx.x * 8 + warp;
    if (node >= Nn) return;
    float wd = g_dinv[node];
    float acc = wd * g_h2[(size_t)node * 32 + lane];
    int beg = g_rowstart[node];
    int cnt = g_deg[node];
    for (int j = 0; j < cnt; j++) {
        int s = g_col[beg + j];
        acc += g_dinv[s] * g_h2[(size_t)s * 32 + lane];
    }
    float r = acc * wd + bias[lane];
    g_x3[(size_t)node * 32 + lane] = fmaxf(r, 0.f);
}

// Layer 3: h = g_h3 (F=16), out = d_out (real harness pointer), no relu.
__global__ void k_agg16(const float* __restrict__ bias, float* __restrict__ out) {
    int tid = threadIdx.x;
    int local = tid & 15;
    int node = blockIdx.x * 16 + (tid >> 4);
    if (node >= Nn) return;
    float wd = g_dinv[node];
    float acc = wd * g_h3[(size_t)node * 16 + local];
    int beg = g_rowstart[node];
    int cnt = g_deg[node];
    for (int j = 0; j < cnt; j++) {
        int s = g_col[beg + j];
        acc += g_dinv[s] * g_h3[(size_t)s * 16 + local];
    }
    out[(size_t)node * 16 + local] = acc * wd + bias[local];
}

// ---------------- launch -----------------------------------------------------
extern "C" void kernel_launch(void* const* d_in, const int* in_sizes, int n_in,
                              void* d_out, int out_size) {
    const float* x   = (const float*)d_in[0];
    const void*  ei  = (const void*)d_in[1];
    const float* W1  = (const float*)d_in[2];
    const float* b1  = (const float*)d_in[3];
    const float* W2  = (const float*)d_in[4];
    const float* b2  = (const float*)d_in[5];
    const float* W3  = (const float*)d_in[6];
    const float* b3  = (const float*)d_in[7];
    float* out       = (float*)d_out;

    const int scanBlocks = (Nn + 1023) / 1024;   // 49

    // dtype detect + CSR + norm build
    k_detect<<<1, 32>>>((const unsigned int*)ei);
    k_zero_deg<<<(Nn + 255) / 256, 256>>>();
    k_count<<<(Ee + 255) / 256, 256>>>(ei);
    k_scan1<<<scanBlocks, 1024>>>();
    k_scan2<<<1, 32>>>(scanBlocks);
    k_scan3<<<(Nn + 255) / 256, 256>>>();
    k_scatter<<<(Ee + 255) / 256, 256>>>(ei);

    // Layer 1
    {
        dim3 grid(H1 / 64, (Nn + 63) / 64);
        k_gemm1<<<grid, 256>>>(x, W1);
    }
    k_agg256<<<(Nn + 7) / 8, 256>>>(b1);

    // Layer 2
    k_gemm2<<<(Nn + 31) / 32, 256>>>(W2);
    k_agg32<<<(Nn + 7) / 8, 256>>>(b2);

    // Layer 3
    k_gemm3<<<(Nn + 255) / 256, 256>>>(W3);
    k_agg16<<<(Nn + 15) / 16, 256>>>(b3, out);
}